// round 14
// baseline (speedup 1.0000x reference)
#include <cuda_runtime.h>
#include <cstdint>
#include <math.h>

// ---------------------------------------------------------------------------
// ChebConv2D  (B=32, C=64, H=W=128, O=64, K=9)
//
//   M [b,c,a,bb]  = sum_h sum_w T[h,a] x[b,c,h,w] T[w,bb]   (k1, recurrence+parity)
//   ch[b,c,kh,kw] = Ginv M Ginv^T                           (k1 tail)
//   Wc[kh,kw,c,f] = sum_o W_w[c,o,kw] * W_h[o,f,kh]         (setup)
//   e [b,f,kh,kw] = sum_c ch[b,c,kh,kw] * Wc[kh,kw,c,f]     (k_mix)
//   out[b,f,h,w]  = Te * e * Te^T                           (k4, recurrence+parity)
//
// R14: k1 re-tiled to 2 cols/thread (float2) to cut regs 90 -> ~52 and lift
// occupancy 31% -> ~60% (k1 was scoreboard-stall bound at 5 blocks/SM).
// ---------------------------------------------------------------------------

#define BB   32
#define CC   64
#define HH   128
#define WW   128
#define OO   64
#define KK   9
#define KK2  81
#define BC   (BB*CC)     // 2048
#define BF   (BB*OO)     // 2048
#define IMG  (HH*WW)     // 16384

__device__ float g_Te[HH*KK];        // T[i][k], i*9+k
__device__ float g_Gi[KK2];          // Ginv[kh][a]
__device__ float g_xn[HH];           // clamped chebyshev abscissae
__device__ float g_ch[KK2*BC];       // [j][b*64+c]
__device__ float g_wc[KK2*CC*OO];    // [j][c][f]
__device__ float g_e [BF*KK2];       // [b*64+f][j]

// ---------------------------------------------------------------------------
// kA: block 0 = Chebyshev setup (fp32, warp-level GJ);
//     blocks 1..81 = combined weight Wc[j][c][f]
// ---------------------------------------------------------------------------
__global__ __launch_bounds__(256) void kA_setup_wc(const float* __restrict__ Ww,
                                                   const float* __restrict__ Wh) {
    int tid = threadIdx.x;

    if (blockIdx.x == 0) {
        __shared__ float Tf[HH*KK];       // T[i][k]
        __shared__ float Gm[KK][19];      // augmented [G | I]

        if (tid < HH) {
            double xd = (double)tid / 127.0;
            float  xf = (float)xd;
            float  xn = 2.0f * xf - 1.0f;
            xn = fminf(fmaxf(xn, -1.0f + 1e-6f), 1.0f - 1e-6f);
            g_xn[tid] = xn;
            float x2 = xn + xn;
            float t0 = 1.0f, t1 = xn;
            Tf[tid*KK + 0] = 1.0f;  g_Te[tid*KK + 0] = 1.0f;
            Tf[tid*KK + 1] = t1;    g_Te[tid*KK + 1] = t1;
            #pragma unroll
            for (int k = 2; k < KK; k++) {
                float t2 = x2*t1 - t0;
                Tf[tid*KK + k] = t2;
                g_Te[tid*KK + k] = t2;
                t0 = t1; t1 = t2;
            }
        }
        __syncthreads();

        if (tid < KK2) {
            int a = tid / KK, b = tid % KK;
            float s0 = 0.f, s1 = 0.f, s2 = 0.f, s3 = 0.f;
            #pragma unroll 4
            for (int j = 0; j < HH; j += 4) {
                s0 += Tf[(j+0)*KK + a] * Tf[(j+0)*KK + b];
                s1 += Tf[(j+1)*KK + a] * Tf[(j+1)*KK + b];
                s2 += Tf[(j+2)*KK + a] * Tf[(j+2)*KK + b];
                s3 += Tf[(j+3)*KK + a] * Tf[(j+3)*KK + b];
            }
            Gm[a][b]     = (s0+s1) + (s2+s3);
            Gm[a][9 + b] = (a == b) ? 1.0f : 0.0f;
        }
        __syncthreads();

        if (tid < 32) {                   // warp-level Gauss-Jordan
            int lane = tid;
            for (int p = 0; p < KK; p++) {
                float pv = Gm[p][p];
                __syncwarp();
                if (lane < 18) Gm[p][lane] /= pv;
                __syncwarp();
                float fac[KK];
                #pragma unroll
                for (int r = 0; r < KK; r++) fac[r] = Gm[r][p];
                __syncwarp();
                if (lane < 18) {
                    #pragma unroll
                    for (int r = 0; r < KK; r++)
                        if (r != p) Gm[r][lane] -= fac[r] * Gm[p][lane];
                }
                __syncwarp();
            }
        }
        __syncthreads();

        if (tid < KK2)
            g_Gi[tid] = Gm[tid / KK][9 + tid % KK];
    } else {
        // Wc[j][c][f] = sum_o Ww[c,o,kw]*Wh[o,f,kh]
        __shared__ float sww[CC*(OO+1)];
        __shared__ float swh[OO*OO];
        int j  = blockIdx.x - 1;
        int kh = j / KK, kw = j % KK;

        for (int i = tid; i < CC*OO; i += 256) {
            int c = i >> 6, o = i & 63;
            sww[c*(OO+1) + o] = Ww[(c*OO + o)*KK + kw];
            swh[i]            = Wh[i*KK + kh];
        }
        __syncthreads();

        int f  = tid & 63;
        int c0 = (tid >> 6) * 16;
        float acc[16];
        #pragma unroll
        for (int i = 0; i < 16; i++) acc[i] = 0.0f;
        for (int o = 0; o < OO; o++) {
            float wh = swh[o*OO + f];
            #pragma unroll
            for (int i = 0; i < 16; i++)
                acc[i] += sww[(c0 + i)*(OO+1) + o] * wh;
        }
        float* wcj = g_wc + (size_t)j * CC * OO;
        #pragma unroll
        for (int i = 0; i < 16; i++)
            wcj[(c0 + i)*OO + f] = acc[i];
    }
}

// ---------------------------------------------------------------------------
// K1: per (b,c) image -> ch[j][bc].  2 cols/thread (float2), batch-4 loads,
// h-recurrence + parity fold.  128 threads = 2 pair-slices x 64 col-slots.
// ---------------------------------------------------------------------------
__global__ __launch_bounds__(128) void k1_analysis(const float* __restrict__ x) {
    __shared__ __align__(16) float red[2*KK*132];  // [s][k][w] 9504 B
    __shared__ float xs[HH];            // xn abscissae
    __shared__ float tew[HH*KK];        // T[w][b] for width-analysis tail
    __shared__ float Ms[KK2];
    __shared__ float tmp[KK2];
    __shared__ float gi[KK2];

    int tid = threadIdx.x;
    int bc  = blockIdx.x;
    int s   = tid >> 6;                 // 0..1 -> pairs [s*32, s*32+32)
    int c0  = (tid & 63) * 2;           // 2 columns per thread

    if (tid < HH) xs[tid] = g_xn[tid];
    for (int i = tid; i < HH*KK; i += 128) tew[i] = g_Te[i];
    if (tid < KK2) gi[tid] = g_Gi[tid];
    __syncthreads();

    const float* xg = x + (size_t)bc * IMG + c0;

    float ax[KK], ay[KK];
    #pragma unroll
    for (int k = 0; k < KK; k++) { ax[k] = 0.0f; ay[k] = 0.0f; }

    // 32 h-pairs in batches of 4: 8 independent LDG.64 in flight per thread.
    #pragma unroll
    for (int pb = 0; pb < 32; pb += 4) {
        float2 lo[4], hi[4];
        #pragma unroll
        for (int q = 0; q < 4; q++) {
            int h = s*32 + pb + q;
            lo[q] = *(const float2*)(xg + h*WW);
            hi[q] = *(const float2*)(xg + (127-h)*WW);
        }
        #pragma unroll
        for (int q = 0; q < 4; q++) {
            int h = s*32 + pb + q;
            float sx = lo[q].x + hi[q].x, sy = lo[q].y + hi[q].y;
            float dx = lo[q].x - hi[q].x, dy = lo[q].y - hi[q].y;
            float xn = xs[h], x2 = xn + xn;
            ax[0] += sx; ay[0] += sy;
            float t0 = 1.0f, t1 = xn;
            ax[1] += t1*dx; ay[1] += t1*dy;
            #pragma unroll
            for (int k = 2; k < KK; k++) {
                float t2 = x2*t1 - t0;
                if ((k & 1) == 0) { ax[k] += t2*sx; ay[k] += t2*sy; }
                else              { ax[k] += t2*dx; ay[k] += t2*dy; }
                t0 = t1; t1 = t2;
            }
        }
    }

    // partials -> smem: red[s][k][w]
    #pragma unroll
    for (int k = 0; k < KK; k++)
        *(float2*)(red + (s*KK + k)*132 + c0) = make_float2(ax[k], ay[k]);
    __syncthreads();

    // reduce 2 slices into slice 0
    {
        int w = tid;                    // 128 threads = 128 w
        #pragma unroll
        for (int k = 0; k < KK; k++)
            red[k*132 + w] = red[k*132 + w] + red[(KK + k)*132 + w];
    }
    __syncthreads();

    // width analysis with w-parity: M[a][b] = sum_{w<64} (red[w] +- red[127-w]) T[w][b]
    if (tid < KK2) {
        int a = tid / KK, b = tid % KK;
        float sgn = (b & 1) ? -1.0f : 1.0f;
        float sum = 0.0f;
        #pragma unroll 4
        for (int w = 0; w < 64; w++) {
            float v = red[a*132 + w] + sgn * red[a*132 + 127 - w];
            sum += v * tew[w*KK + b];
        }
        Ms[tid] = sum;
    }
    __syncthreads();

    // ch = Ginv * M * Ginv^T
    if (tid < KK2) {
        int kh = tid / KK, b = tid % KK;
        float sum = 0.0f;
        #pragma unroll
        for (int a = 0; a < KK; a++)
            sum += gi[kh*KK + a] * Ms[a*KK + b];
        tmp[tid] = sum;
    }
    __syncthreads();
    if (tid < KK2) {
        int kh = tid / KK, kw = tid % KK;
        float sum = 0.0f;
        #pragma unroll
        for (int b = 0; b < KK; b++)
            sum += tmp[kh*KK + b] * gi[kw*KK + b];
        g_ch[(size_t)tid * BC + bc] = sum;
    }
}

// ---------------------------------------------------------------------------
// K_mix: e[b,f,j] = sum_c ch[j][b,c] * Wc[j][c][f].
// grid = 81 j * 4 b-groups (8 b each); 256 threads: (f, 4 b-pairs)
// ---------------------------------------------------------------------------
__global__ __launch_bounds__(256) void k_mix() {
    __shared__ float chs[8*CC];        // [bl][c]
    __shared__ float wcs[CC*OO];       // [c][f]
    int tid = threadIdx.x;
    int j   = blockIdx.x >> 2;
    int b0  = (blockIdx.x & 3) * 8;

    for (int i = tid; i < 8*CC; i += 256)
        chs[i] = g_ch[(size_t)j * BC + b0*CC + i];
    for (int i = tid; i < CC*OO; i += 256)
        wcs[i] = g_wc[(size_t)j * CC * OO + i];
    __syncthreads();

    int f  = tid & 63;
    int bl = (tid >> 6) * 2;
    float a0 = 0.0f, a1 = 0.0f;
    #pragma unroll 8
    for (int c = 0; c < CC; c++) {
        float wv = wcs[c*OO + f];
        a0 += chs[bl*CC + c]     * wv;
        a1 += chs[(bl+1)*CC + c] * wv;
    }
    g_e[(size_t)((b0 + bl    )*OO + f) * KK2 + j] = a0;
    g_e[(size_t)((b0 + bl + 1)*OO + f) * KK2 + j] = a1;
}

// ---------------------------------------------------------------------------
// K4: out = Te * e * Te^T with parity on h.
// one block per (b,f); 256 threads = (4 w's, 8 h-pairs); float4 stores.
// ---------------------------------------------------------------------------
__global__ __launch_bounds__(256) void k4_synth(float* __restrict__ out) {
    __shared__ __align__(16) float vs[KK*132];     // [kh][w] padded
    __shared__ float es[KK2];
    __shared__ float xs[HH];
    int tid = threadIdx.x;
    int bf  = blockIdx.x;

    if (tid < HH) xs[tid] = g_xn[tid];
    if (tid >= 128 && tid < 128 + KK2) es[tid-128] = g_e[(size_t)bf * KK2 + (tid-128)];
    __syncthreads();

    // v[kh][w] via width recurrence; all 256 threads (kh split 0..3 / 4..8)
    {
        int w  = tid & 127;
        int hi = tid >> 7;
        float xn = xs[w], x2 = xn + xn;
        float tw[KK];
        tw[0] = 1.0f; tw[1] = xn;
        #pragma unroll
        for (int k = 2; k < KK; k++) tw[k] = x2*tw[k-1] - tw[k-2];
        int kh0 = hi ? 4 : 0;
        int kh1 = hi ? 9 : 4;
        for (int kh = kh0; kh < kh1; kh++) {
            float sv = 0.0f;
            #pragma unroll
            for (int kw = 0; kw < KK; kw++) sv += es[kh*KK + kw] * tw[kw];
            vs[kh*132 + w] = sv;
        }
    }
    __syncthreads();

    int w4 = (tid & 31) * 4;
    int s  = tid >> 5;                  // 0..7 -> h pairs [s*8, s*8+8)
    float4 vr[KK];
    #pragma unroll
    for (int k = 0; k < KK; k++) vr[k] = *(const float4*)(vs + k*132 + w4);

    float* op = out + (size_t)bf * IMG + w4;
    #pragma unroll 4
    for (int pp = 0; pp < 8; pp++) {
        int h = s*8 + pp;               // lo row; hi = 127-h
        float xn = xs[h], x2 = xn + xn;
        float4 E, O;
        E.x = vr[0].x; E.y = vr[0].y; E.z = vr[0].z; E.w = vr[0].w;
        float t0 = 1.0f, t1 = xn;
        O.x = t1*vr[1].x; O.y = t1*vr[1].y; O.z = t1*vr[1].z; O.w = t1*vr[1].w;
        #pragma unroll
        for (int k = 2; k < KK; k++) {
            float t2 = x2*t1 - t0;
            if ((k & 1) == 0) {
                E.x += t2*vr[k].x; E.y += t2*vr[k].y;
                E.z += t2*vr[k].z; E.w += t2*vr[k].w;
            } else {
                O.x += t2*vr[k].x; O.y += t2*vr[k].y;
                O.z += t2*vr[k].z; O.w += t2*vr[k].w;
            }
            t0 = t1; t1 = t2;
        }
        float4 lo, hi;
        lo.x = E.x + O.x; lo.y = E.y + O.y; lo.z = E.z + O.z; lo.w = E.w + O.w;
        hi.x = E.x - O.x; hi.y = E.y - O.y; hi.z = E.z - O.z; hi.w = E.w - O.w;
        *(float4*)(op + h*WW)       = lo;
        *(float4*)(op + (127-h)*WW) = hi;
    }
}

// ---------------------------------------------------------------------------
extern "C" void kernel_launch(void* const* d_in, const int* in_sizes, int n_in,
                              void* d_out, int out_size) {
    const float* x  = (const float*)d_in[0];
    const float* Ww = (const float*)d_in[1];
    const float* Wh = (const float*)d_in[2];
    float* out = (float*)d_out;

    kA_setup_wc<<<1 + KK2, 256>>>(Ww, Wh);
    k1_analysis<<<BC, 128>>>(x);
    k_mix<<<KK2*4, 256>>>();
    k4_synth<<<BF, 256>>>(out);
}

// round 15
// speedup vs baseline: 1.0922x; 1.0922x over previous
#include <cuda_runtime.h>
#include <cstdint>
#include <math.h>

// ---------------------------------------------------------------------------
// ChebConv2D  (B=32, C=64, H=W=128, O=64, K=9)  -- 3-launch pipeline
//
//  L1 (merged): blk0 Gi=(T^T T)^-1 + flag | blks1..2048 M=T^T x T -> ch (R9 body,
//               in-block tables, tail spins on flag) | blks 2049.. Wc
//  L2: e[b,f,j] = sum_c ch[j][b,c] * Wc[j][c][f]
//  L3: out = Te e Te^T (recurrence + parity)
// ---------------------------------------------------------------------------

#define BB   32
#define CC   64
#define HH   128
#define WW   128
#define OO   64
#define KK   9
#define KK2  81
#define BC   (BB*CC)     // 2048
#define BF   (BB*OO)     // 2048
#define IMG  (HH*WW)     // 16384

__device__ float g_Gi[KK2];          // Ginv[kh][a]
__device__ int   g_flag = 0;         // Gi-ready flag (benign across replays)
__device__ float g_ch[KK2*BC];       // [j][b*64+c]
__device__ float g_wc[KK2*CC*OO];    // [j][c][f]
__device__ float g_e [BF*KK2];       // [b*64+f][j]

__device__ __forceinline__ float xn_of(int i) {
    double xd = (double)i / 127.0;
    float  xf = (float)xd;
    float  v  = 2.0f * xf - 1.0f;
    return fminf(fmaxf(v, -1.0f + 1e-6f), 1.0f - 1e-6f);
}

// ---------------------------------------------------------------------------
// L1: heterogeneous. blk0: Gi+flag. blks 1..2048: analysis. blks 2049..: Wc.
// ---------------------------------------------------------------------------
__global__ __launch_bounds__(128) void kM1(const float* __restrict__ x,
                                           const float* __restrict__ Ww,
                                           const float* __restrict__ Wh) {
    int tid = threadIdx.x;
    int bid = blockIdx.x;

    if (bid == 0) {
        // ---------------- Gi = (T^T T)^-1, then release flag ---------------
        __shared__ float Tf[HH*KK];
        __shared__ float Gm[KK][19];

        if (tid < HH) {
            float xn = xn_of(tid);
            float x2 = xn + xn, t0 = 1.0f, t1 = xn;
            Tf[tid*KK + 0] = 1.0f;
            Tf[tid*KK + 1] = xn;
            #pragma unroll
            for (int k = 2; k < KK; k++) {
                float t2 = x2*t1 - t0;
                Tf[tid*KK + k] = t2;
                t0 = t1; t1 = t2;
            }
        }
        __syncthreads();

        if (tid < KK2) {
            int a = tid / KK, b = tid % KK;
            float s0 = 0.f, s1 = 0.f, s2 = 0.f, s3 = 0.f;
            #pragma unroll 4
            for (int j = 0; j < HH; j += 4) {
                s0 += Tf[(j+0)*KK + a] * Tf[(j+0)*KK + b];
                s1 += Tf[(j+1)*KK + a] * Tf[(j+1)*KK + b];
                s2 += Tf[(j+2)*KK + a] * Tf[(j+2)*KK + b];
                s3 += Tf[(j+3)*KK + a] * Tf[(j+3)*KK + b];
            }
            Gm[a][b]     = (s0+s1) + (s2+s3);
            Gm[a][9 + b] = (a == b) ? 1.0f : 0.0f;
        }
        __syncthreads();

        if (tid < 32) {                 // warp-level Gauss-Jordan (SPD)
            int lane = tid;
            for (int p = 0; p < KK; p++) {
                float pv = Gm[p][p];
                __syncwarp();
                if (lane < 18) Gm[p][lane] /= pv;
                __syncwarp();
                float fac[KK];
                #pragma unroll
                for (int r = 0; r < KK; r++) fac[r] = Gm[r][p];
                __syncwarp();
                if (lane < 18) {
                    #pragma unroll
                    for (int r = 0; r < KK; r++)
                        if (r != p) Gm[r][lane] -= fac[r] * Gm[p][lane];
                }
                __syncwarp();
            }
        }
        __syncthreads();

        if (tid < KK2) g_Gi[tid] = Gm[tid / KK][9 + tid % KK];
        __syncthreads();
        __threadfence();                // release Gi before flag
        if (tid == 0) *(volatile int*)&g_flag = 1;

    } else if (bid <= BC) {
        // ---------------- analysis for one (b,c): R9 body ------------------
        __shared__ __align__(16) float red[4*KK*132];   // [s][k][w]
        __shared__ float xs[HH];
        __shared__ float tew[HH*KK];
        __shared__ float Ms[KK2];
        __shared__ float tmp[KK2];
        __shared__ float gi[KK2];

        int bc   = bid - 1;
        int s    = tid >> 5;            // 0..3 -> h pairs [s*16, s*16+16)
        int w4   = (tid & 31) * 4;

        if (tid < HH) {                 // in-block tables via recurrence
            float xn = xn_of(tid);
            xs[tid] = xn;
            float x2 = xn + xn, t0 = 1.0f, t1 = xn;
            tew[tid*KK + 0] = 1.0f;
            tew[tid*KK + 1] = xn;
            #pragma unroll
            for (int k = 2; k < KK; k++) {
                float t2 = x2*t1 - t0;
                tew[tid*KK + k] = t2;
                t0 = t1; t1 = t2;
            }
        }
        __syncthreads();

        const float* xg = x + (size_t)bc * IMG + w4;

        float acc[KK][4];
        #pragma unroll
        for (int k = 0; k < KK; k++)
            #pragma unroll
            for (int i = 0; i < 4; i++) acc[k][i] = 0.0f;

        // 16 h-pairs in batches of 4: 8 independent LDG.128 in flight.
        #pragma unroll
        for (int pb = 0; pb < 16; pb += 4) {
            float4 lo[4], hi[4];
            #pragma unroll
            for (int q = 0; q < 4; q++) {
                int h = s*16 + pb + q;
                lo[q] = *(const float4*)(xg + h*WW);
                hi[q] = *(const float4*)(xg + (127-h)*WW);
            }
            #pragma unroll
            for (int q = 0; q < 4; q++) {
                int h = s*16 + pb + q;
                float sx = lo[q].x + hi[q].x, sy = lo[q].y + hi[q].y;
                float sz = lo[q].z + hi[q].z, sw = lo[q].w + hi[q].w;
                float dx = lo[q].x - hi[q].x, dy = lo[q].y - hi[q].y;
                float dz = lo[q].z - hi[q].z, dw = lo[q].w - hi[q].w;
                float xn = xs[h], x2 = xn + xn;
                acc[0][0] += sx; acc[0][1] += sy; acc[0][2] += sz; acc[0][3] += sw;
                float t0 = 1.0f, t1 = xn;
                acc[1][0] += t1*dx; acc[1][1] += t1*dy; acc[1][2] += t1*dz; acc[1][3] += t1*dw;
                #pragma unroll
                for (int k = 2; k < KK; k++) {
                    float t2 = x2*t1 - t0;
                    if ((k & 1) == 0) {
                        acc[k][0] += t2*sx; acc[k][1] += t2*sy;
                        acc[k][2] += t2*sz; acc[k][3] += t2*sw;
                    } else {
                        acc[k][0] += t2*dx; acc[k][1] += t2*dy;
                        acc[k][2] += t2*dz; acc[k][3] += t2*dw;
                    }
                    t0 = t1; t1 = t2;
                }
            }
        }

        #pragma unroll
        for (int k = 0; k < KK; k++)
            *(float4*)(red + (s*KK + k)*132 + w4) =
                make_float4(acc[k][0], acc[k][1], acc[k][2], acc[k][3]);
        __syncthreads();

        {   // reduce 4 slices into slice 0
            int w = tid;
            #pragma unroll
            for (int k = 0; k < KK; k++) {
                float v = red[(0*KK + k)*132 + w] + red[(1*KK + k)*132 + w]
                        + red[(2*KK + k)*132 + w] + red[(3*KK + k)*132 + w];
                red[k*132 + w] = v;
            }
        }
        __syncthreads();

        // width analysis with w-parity
        if (tid < KK2) {
            int a = tid / KK, b = tid % KK;
            float sgn = (b & 1) ? -1.0f : 1.0f;
            float sum = 0.0f;
            #pragma unroll 4
            for (int w = 0; w < 64; w++) {
                float v = red[a*132 + w] + sgn * red[a*132 + 127 - w];
                sum += v * tew[w*KK + b];
            }
            Ms[tid] = sum;
        }

        // wait for Gi (block 0 finishes in wave 1, long before any tail)
        if (tid == 0) {
            while (*(volatile int*)&g_flag == 0) { }
        }
        __syncthreads();
        if (tid < KK2) gi[tid] = __ldcg(&g_Gi[tid]);
        __syncthreads();

        // ch = Ginv * M * Ginv^T
        if (tid < KK2) {
            int kh = tid / KK, b = tid % KK;
            float sum = 0.0f;
            #pragma unroll
            for (int a = 0; a < KK; a++)
                sum += gi[kh*KK + a] * Ms[a*KK + b];
            tmp[tid] = sum;
        }
        __syncthreads();
        if (tid < KK2) {
            int kh = tid / KK, kw = tid % KK;
            float sum = 0.0f;
            #pragma unroll
            for (int b = 0; b < KK; b++)
                sum += tmp[kh*KK + b] * gi[kw*KK + b];
            g_ch[(size_t)tid * BC + bc] = sum;
        }

    } else {
        // ---------------- Wc[j][c][f] = sum_o Ww[c,o,kw]*Wh[o,f,kh] --------
        __shared__ float sww[CC*(OO+1)];
        __shared__ float swh[OO*OO];
        int j  = bid - BC - 1;          // 0..80
        int kh = j / KK, kw = j % KK;

        for (int i = tid; i < CC*OO; i += 128) {
            int c = i >> 6, o = i & 63;
            sww[c*(OO+1) + o] = Ww[(c*OO + o)*KK + kw];
            swh[i]            = Wh[i*KK + kh];
        }
        __syncthreads();

        int f    = tid & 63;
        int half = tid >> 6;            // 0..1
        float* wcj = g_wc + (size_t)j * CC * OO;
        #pragma unroll
        for (int cb = 0; cb < 2; cb++) {
            int c0 = half*32 + cb*16;
            float acc[16];
            #pragma unroll
            for (int i = 0; i < 16; i++) acc[i] = 0.0f;
            for (int o = 0; o < OO; o++) {
                float wh = swh[o*OO + f];
                #pragma unroll
                for (int i = 0; i < 16; i++)
                    acc[i] += sww[(c0 + i)*(OO+1) + o] * wh;
            }
            #pragma unroll
            for (int i = 0; i < 16; i++)
                wcj[(c0 + i)*OO + f] = acc[i];
        }
    }
}

// ---------------------------------------------------------------------------
// L2: e[b,f,j] = sum_c ch[j][b,c] * Wc[j][c][f].
// grid = 81 j * 4 b-groups (8 b each); 256 threads: (f, 4 b-pairs)
// ---------------------------------------------------------------------------
__global__ __launch_bounds__(256) void k_mix() {
    __shared__ float chs[8*CC];        // [bl][c]
    __shared__ float wcs[CC*OO];       // [c][f]
    int tid = threadIdx.x;
    int j   = blockIdx.x >> 2;
    int b0  = (blockIdx.x & 3) * 8;

    for (int i = tid; i < 8*CC; i += 256)
        chs[i] = g_ch[(size_t)j * BC + b0*CC + i];
    for (int i = tid; i < CC*OO; i += 256)
        wcs[i] = g_wc[(size_t)j * CC * OO + i];
    __syncthreads();

    int f  = tid & 63;
    int bl = (tid >> 6) * 2;
    float a0 = 0.0f, a1 = 0.0f;
    #pragma unroll 8
    for (int c = 0; c < CC; c++) {
        float wv = wcs[c*OO + f];
        a0 += chs[bl*CC + c]     * wv;
        a1 += chs[(bl+1)*CC + c] * wv;
    }
    g_e[(size_t)((b0 + bl    )*OO + f) * KK2 + j] = a0;
    g_e[(size_t)((b0 + bl + 1)*OO + f) * KK2 + j] = a1;
}

// ---------------------------------------------------------------------------
// L3: out = Te * e * Te^T with parity on h; tables in-block.
// one block per (b,f); 256 threads = (4 w's, 8 h-pairs); float4 stores.
// ---------------------------------------------------------------------------
__global__ __launch_bounds__(256) void k4_synth(float* __restrict__ out) {
    __shared__ __align__(16) float vs[KK*132];     // [kh][w] padded
    __shared__ float es[KK2];
    __shared__ float xs[HH];
    int tid = threadIdx.x;
    int bf  = blockIdx.x;

    if (tid < HH) xs[tid] = xn_of(tid);
    if (tid >= 128 && tid < 128 + KK2) es[tid-128] = g_e[(size_t)bf * KK2 + (tid-128)];
    __syncthreads();

    // v[kh][w] via width recurrence; all 256 threads (kh split 0..3 / 4..8)
    {
        int w  = tid & 127;
        int hi = tid >> 7;
        float xn = xs[w], x2 = xn + xn;
        float tw[KK];
        tw[0] = 1.0f; tw[1] = xn;
        #pragma unroll
        for (int k = 2; k < KK; k++) tw[k] = x2*tw[k-1] - tw[k-2];
        int kh0 = hi ? 4 : 0;
        int kh1 = hi ? 9 : 4;
        for (int kh = kh0; kh < kh1; kh++) {
            float sv = 0.0f;
            #pragma unroll
            for (int kw = 0; kw < KK; kw++) sv += es[kh*KK + kw] * tw[kw];
            vs[kh*132 + w] = sv;
        }
    }
    __syncthreads();

    int w4 = (tid & 31) * 4;
    int s  = tid >> 5;                  // 0..7 -> h pairs [s*8, s*8+8)
    float4 vr[KK];
    #pragma unroll
    for (int k = 0; k < KK; k++) vr[k] = *(const float4*)(vs + k*132 + w4);

    float* op = out + (size_t)bf * IMG + w4;
    #pragma unroll 4
    for (int pp = 0; pp < 8; pp++) {
        int h = s*8 + pp;               // lo row; hi = 127-h
        float xn = xs[h], x2 = xn + xn;
        float4 E, O;
        E.x = vr[0].x; E.y = vr[0].y; E.z = vr[0].z; E.w = vr[0].w;
        float t0 = 1.0f, t1 = xn;
        O.x = t1*vr[1].x; O.y = t1*vr[1].y; O.z = t1*vr[1].z; O.w = t1*vr[1].w;
        #pragma unroll
        for (int k = 2; k < KK; k++) {
            float t2 = x2*t1 - t0;
            if ((k & 1) == 0) {
                E.x += t2*vr[k].x; E.y += t2*vr[k].y;
                E.z += t2*vr[k].z; E.w += t2*vr[k].w;
            } else {
                O.x += t2*vr[k].x; O.y += t2*vr[k].y;
                O.z += t2*vr[k].z; O.w += t2*vr[k].w;
            }
            t0 = t1; t1 = t2;
        }
        float4 lo, hi;
        lo.x = E.x + O.x; lo.y = E.y + O.y; lo.z = E.z + O.z; lo.w = E.w + O.w;
        hi.x = E.x - O.x; hi.y = E.y - O.y; hi.z = E.z - O.z; hi.w = E.w - O.w;
        *(float4*)(op + h*WW)       = lo;
        *(float4*)(op + (127-h)*WW) = hi;
    }
}

// ---------------------------------------------------------------------------
extern "C" void kernel_launch(void* const* d_in, const int* in_sizes, int n_in,
                              void* d_out, int out_size) {
    const float* x  = (const float*)d_in[0];
    const float* Ww = (const float*)d_in[1];
    const float* Wh = (const float*)d_in[2];
    float* out = (float*)d_out;

    kM1<<<1 + BC + KK2, 128>>>(x, Ww, Wh);
    k_mix<<<KK2*4, 256>>>();
    k4_synth<<<BF, 256>>>(out);
}

// round 17
// speedup vs baseline: 1.1447x; 1.0481x over previous
#include <cuda_runtime.h>
#include <cstdint>
#include <math.h>

// ---------------------------------------------------------------------------
// ChebConv2D  (B=32, C=64, H=W=128, O=64, K=9)
//
//   M [b,c,a,bb]  = sum_h sum_w T[h,a] x[b,c,h,w] T[w,bb]   (k1)
//   ch[b,c,kh,kw] = Ginv M Ginv^T                           (k1 tail)
//   Wc[kh,kw,c,f] = sum_o W_w[c,o,kw] * W_h[o,f,kh]         (setup)
//   e [b,f,kh,kw] = sum_c ch[b,c,kh,kw] * Wc[kh,kw,c,f]     (k_mix)
//   out[b,f,h,w]  = Te * e * Te^T                           (k4)
//
// R16/R17: k1 = sync-free per-warp cp.async ring. Each lane cp.asyncs exactly
// the 16B it consumes (completion is per-thread), 4-deep ring -> 8KB in flight
// per warp continuously, zero barriers in the main loop. (k1 was duty-cycle
// bound: bursty loads + long waits at any occupancy.)
// ---------------------------------------------------------------------------

#define BB   32
#define CC   64
#define HH   128
#define WW   128
#define OO   64
#define KK   9
#define KK2  81
#define BC   (BB*CC)     // 2048
#define BF   (BB*OO)     // 2048
#define IMG  (HH*WW)     // 16384

__device__ float g_Te[HH*KK];        // T[i][k], i*9+k
__device__ float g_Gi[KK2];          // Ginv[kh][a]
__device__ float g_xn[HH];           // clamped chebyshev abscissae
__device__ float g_ch[KK2*BC];       // [j][b*64+c]
__device__ float g_wc[KK2*CC*OO];    // [j][c][f]
__device__ float g_e [BF*KK2];       // [b*64+f][j]

// ---------------------------------------------------------------------------
// kA: block 0 = Chebyshev setup (fp32, warp-level GJ);
//     blocks 1..81 = combined weight Wc[j][c][f]
// ---------------------------------------------------------------------------
__global__ __launch_bounds__(256) void kA_setup_wc(const float* __restrict__ Ww,
                                                   const float* __restrict__ Wh) {
    int tid = threadIdx.x;

    if (blockIdx.x == 0) {
        __shared__ float Tf[HH*KK];       // T[i][k]
        __shared__ float Gm[KK][19];      // augmented [G | I]

        if (tid < HH) {
            double xd = (double)tid / 127.0;
            float  xf = (float)xd;
            float  xn = 2.0f * xf - 1.0f;
            xn = fminf(fmaxf(xn, -1.0f + 1e-6f), 1.0f - 1e-6f);
            g_xn[tid] = xn;
            float x2 = xn + xn;
            float t0 = 1.0f, t1 = xn;
            Tf[tid*KK + 0] = 1.0f;  g_Te[tid*KK + 0] = 1.0f;
            Tf[tid*KK + 1] = t1;    g_Te[tid*KK + 1] = t1;
            #pragma unroll
            for (int k = 2; k < KK; k++) {
                float t2 = x2*t1 - t0;
                Tf[tid*KK + k] = t2;
                g_Te[tid*KK + k] = t2;
                t0 = t1; t1 = t2;
            }
        }
        __syncthreads();

        if (tid < KK2) {
            int a = tid / KK, b = tid % KK;
            float s0 = 0.f, s1 = 0.f, s2 = 0.f, s3 = 0.f;
            #pragma unroll 4
            for (int j = 0; j < HH; j += 4) {
                s0 += Tf[(j+0)*KK + a] * Tf[(j+0)*KK + b];
                s1 += Tf[(j+1)*KK + a] * Tf[(j+1)*KK + b];
                s2 += Tf[(j+2)*KK + a] * Tf[(j+2)*KK + b];
                s3 += Tf[(j+3)*KK + a] * Tf[(j+3)*KK + b];
            }
            Gm[a][b]     = (s0+s1) + (s2+s3);
            Gm[a][9 + b] = (a == b) ? 1.0f : 0.0f;
        }
        __syncthreads();

        if (tid < 32) {                   // warp-level Gauss-Jordan
            int lane = tid;
            for (int p = 0; p < KK; p++) {
                float pv = Gm[p][p];
                __syncwarp();
                if (lane < 18) Gm[p][lane] /= pv;
                __syncwarp();
                float fac[KK];
                #pragma unroll
                for (int r = 0; r < KK; r++) fac[r] = Gm[r][p];
                __syncwarp();
                if (lane < 18) {
                    #pragma unroll
                    for (int r = 0; r < KK; r++)
                        if (r != p) Gm[r][lane] -= fac[r] * Gm[p][lane];
                }
                __syncwarp();
            }
        }
        __syncthreads();

        if (tid < KK2)
            g_Gi[tid] = Gm[tid / KK][9 + tid % KK];
    } else {
        // Wc[j][c][f] = sum_o Ww[c,o,kw]*Wh[o,f,kh]
        __shared__ float sww[CC*(OO+1)];
        __shared__ float swh[OO*OO];
        int j  = blockIdx.x - 1;
        int kh = j / KK, kw = j % KK;

        for (int i = tid; i < CC*OO; i += 256) {
            int c = i >> 6, o = i & 63;
            sww[c*(OO+1) + o] = Ww[(c*OO + o)*KK + kw];
            swh[i]            = Wh[i*KK + kh];
        }
        __syncthreads();

        int f  = tid & 63;
        int c0 = (tid >> 6) * 16;
        float acc[16];
        #pragma unroll
        for (int i = 0; i < 16; i++) acc[i] = 0.0f;
        for (int o = 0; o < OO; o++) {
            float wh = swh[o*OO + f];
            #pragma unroll
            for (int i = 0; i < 16; i++)
                acc[i] += sww[(c0 + i)*(OO+1) + o] * wh;
        }
        float* wcj = g_wc + (size_t)j * CC * OO;
        #pragma unroll
        for (int i = 0; i < 16; i++)
            wcj[(c0 + i)*OO + f] = acc[i];
    }
}

// ---------------------------------------------------------------------------
// K1: per (b,c) image -> ch[j][bc].
// 128 threads = 4 warps; warp owns 16 h-pairs in 8 chunks of 2 pairs.
// Per-warp 4-slot cp.async ring, zero barriers in the main loop:
// lane L stages and consumes exactly bytes [16L,16L+16) of each row.
// ---------------------------------------------------------------------------
__device__ __forceinline__ void k1_issue(unsigned sb, const float* xg,
                                         int warp, int lane, int c) {
    int p0 = warp*16 + c*2;
    unsigned dst = sb + (unsigned)((c & 3)*2048 + lane*16);   // bytes
    const float* base = xg + lane*4;
    asm volatile("cp.async.cg.shared.global [%0], [%1], 16;"
        :: "r"(dst),        "l"(base + p0*WW));
    asm volatile("cp.async.cg.shared.global [%0], [%1], 16;"
        :: "r"(dst + 512),  "l"(base + (p0+1)*WW));
    asm volatile("cp.async.cg.shared.global [%0], [%1], 16;"
        :: "r"(dst + 1024), "l"(base + (127-p0)*WW));
    asm volatile("cp.async.cg.shared.global [%0], [%1], 16;"
        :: "r"(dst + 1536), "l"(base + (126-p0)*WW));
    asm volatile("cp.async.commit_group;");
}

__global__ __launch_bounds__(128) void k1_analysis(const float* __restrict__ x) {
    __shared__ __align__(16) float bufs[4*2048];   // 4 warps x 4 slots x 4 rows x 128
    __shared__ float xs[HH];
    __shared__ float tew[HH*KK];
    __shared__ float Ms[KK2];
    __shared__ float tmp[KK2];
    __shared__ float gi[KK2];

    int tid  = threadIdx.x;
    int bc   = blockIdx.x;
    int warp = tid >> 5;
    int lane = tid & 31;

    if (tid < HH) xs[tid] = g_xn[tid];
    for (int i = tid; i < HH*KK; i += 128) tew[i] = g_Te[i];
    if (tid < KK2) gi[tid] = g_Gi[tid];

    const float* xg = x + (size_t)bc * IMG;
    float* wb = bufs + warp*2048;
    unsigned sb = (unsigned)__cvta_generic_to_shared(wb);

    // prologue: 4 chunks in flight
    k1_issue(sb, xg, warp, lane, 0);
    k1_issue(sb, xg, warp, lane, 1);
    k1_issue(sb, xg, warp, lane, 2);
    k1_issue(sb, xg, warp, lane, 3);

    __syncthreads();                       // xs/tew/gi ready (overlapped w/ fills)

    float acc[KK][4];
    #pragma unroll
    for (int k = 0; k < KK; k++)
        #pragma unroll
        for (int i = 0; i < 4; i++) acc[k][i] = 0.0f;

    #pragma unroll
    for (int c = 0; c < 8; c++) {
        if (c < 5)       asm volatile("cp.async.wait_group 3;");
        else if (c == 5) asm volatile("cp.async.wait_group 2;");
        else if (c == 6) asm volatile("cp.async.wait_group 1;");
        else             asm volatile("cp.async.wait_group 0;");

        int slot = c & 3;
        #pragma unroll
        for (int i = 0; i < 2; i++) {
            float4 lo = *(const float4*)(wb + slot*512 + i*128       + lane*4);
            float4 hi = *(const float4*)(wb + slot*512 + (2+i)*128   + lane*4);
            float sx = lo.x + hi.x, sy = lo.y + hi.y;
            float sz = lo.z + hi.z, sw = lo.w + hi.w;
            float dx = lo.x - hi.x, dy = lo.y - hi.y;
            float dz = lo.z - hi.z, dw = lo.w - hi.w;
            float xn = xs[warp*16 + c*2 + i], x2 = xn + xn;
            acc[0][0] += sx; acc[0][1] += sy; acc[0][2] += sz; acc[0][3] += sw;
            float t0 = 1.0f, t1 = xn;
            acc[1][0] += t1*dx; acc[1][1] += t1*dy; acc[1][2] += t1*dz; acc[1][3] += t1*dw;
            #pragma unroll
            for (int k = 2; k < KK; k++) {
                float t2 = x2*t1 - t0;
                if ((k & 1) == 0) {
                    acc[k][0] += t2*sx; acc[k][1] += t2*sy;
                    acc[k][2] += t2*sz; acc[k][3] += t2*sw;
                } else {
                    acc[k][0] += t2*dx; acc[k][1] += t2*dy;
                    acc[k][2] += t2*dz; acc[k][3] += t2*dw;
                }
                t0 = t1; t1 = t2;
            }
        }
        if (c + 4 < 8) k1_issue(sb, xg, warp, lane, c + 4);
    }

    __syncthreads();                       // all buffer reads done before alias

    // partials -> red (aliases bufs): red[warp][k][132]
    float* red = bufs;
    #pragma unroll
    for (int k = 0; k < KK; k++)
        *(float4*)(red + (warp*KK + k)*132 + lane*4) =
            make_float4(acc[k][0], acc[k][1], acc[k][2], acc[k][3]);
    __syncthreads();

    // reduce 4 warp slices into slice 0
    {
        int w = tid;                       // 128 threads = 128 w
        #pragma unroll
        for (int k = 0; k < KK; k++) {
            float v = red[(0*KK + k)*132 + w] + red[(1*KK + k)*132 + w]
                    + red[(2*KK + k)*132 + w] + red[(3*KK + k)*132 + w];
            red[k*132 + w] = v;
        }
    }
    __syncthreads();

    // width analysis with w-parity: M[a][b] = sum_{w<64} (red[w] +- red[127-w]) T[w][b]
    if (tid < KK2) {
        int a = tid / KK, b = tid % KK;
        float sgn = (b & 1) ? -1.0f : 1.0f;
        float sum = 0.0f;
        #pragma unroll 4
        for (int w = 0; w < 64; w++) {
            float v = red[a*132 + w] + sgn * red[a*132 + 127 - w];
            sum += v * tew[w*KK + b];
        }
        Ms[tid] = sum;
    }
    __syncthreads();

    // ch = Ginv * M * Ginv^T
    if (tid < KK2) {
        int kh = tid / KK, b = tid % KK;
        float sum = 0.0f;
        #pragma unroll
        for (int a = 0; a < KK; a++)
            sum += gi[kh*KK + a] * Ms[a*KK + b];
        tmp[tid] = sum;
    }
    __syncthreads();
    if (tid < KK2) {
        int kh = tid / KK, kw = tid % KK;
        float sum = 0.0f;
        #pragma unroll
        for (int b = 0; b < KK; b++)
            sum += tmp[kh*KK + b] * gi[kw*KK + b];
        g_ch[(size_t)tid * BC + bc] = sum;
    }
}

// ---------------------------------------------------------------------------
// K_mix: e[b,f,j] = sum_c ch[j][b,c] * Wc[j][c][f].
// grid = 81 j * 4 b-groups (8 b each); 256 threads: (f, 4 b-pairs)
// ---------------------------------------------------------------------------
__global__ __launch_bounds__(256) void k_mix() {
    __shared__ float chs[8*CC];        // [bl][c]
    __shared__ float wcs[CC*OO];       // [c][f]
    int tid = threadIdx.x;
    int j   = blockIdx.x >> 2;
    int b0  = (blockIdx.x & 3) * 8;

    for (int i = tid; i < 8*CC; i += 256)
        chs[i] = g_ch[(size_t)j * BC + b0*CC + i];
    for (int i = tid; i < CC*OO; i += 256)
        wcs[i] = g_wc[(size_t)j * CC * OO + i];
    __syncthreads();

    int f  = tid & 63;
    int bl = (tid >> 6) * 2;
    float a0 = 0.0f, a1 = 0.0f;
    #pragma unroll 8
    for (int c = 0; c < CC; c++) {
        float wv = wcs[c*OO + f];
        a0 += chs[bl*CC + c]     * wv;
        a1 += chs[(bl+1)*CC + c] * wv;
    }
    g_e[(size_t)((b0 + bl    )*OO + f) * KK2 + j] = a0;
    g_e[(size_t)((b0 + bl + 1)*OO + f) * KK2 + j] = a1;
}

// ---------------------------------------------------------------------------
// K4: out = Te * e * Te^T with parity on h.
// one block per (b,f); 256 threads = (4 w's, 8 h-pairs); float4 stores.
// ---------------------------------------------------------------------------
__global__ __launch_bounds__(256) void k4_synth(float* __restrict__ out) {
    __shared__ __align__(16) float vs[KK*132];     // [kh][w] padded
    __shared__ float es[KK2];
    __shared__ float xs[HH];
    int tid = threadIdx.x;
    int bf  = blockIdx.x;

    if (tid < HH) xs[tid] = g_xn[tid];
    if (tid >= 128 && tid < 128 + KK2) es[tid-128] = g_e[(size_t)bf * KK2 + (tid-128)];
    __syncthreads();

    // v[kh][w] via width recurrence; all 256 threads (kh split 0..3 / 4..8)
    {
        int w  = tid & 127;
        int hi = tid >> 7;
        float xn = xs[w], x2 = xn + xn;
        float tw[KK];
        tw[0] = 1.0f; tw[1] = xn;
        #pragma unroll
        for (int k = 2; k < KK; k++) tw[k] = x2*tw[k-1] - tw[k-2];
        int kh0 = hi ? 4 : 0;
        int kh1 = hi ? 9 : 4;
        for (int kh = kh0; kh < kh1; kh++) {
            float sv = 0.0f;
            #pragma unroll
            for (int kw = 0; kw < KK; kw++) sv += es[kh*KK + kw] * tw[kw];
            vs[kh*132 + w] = sv;
        }
    }
    __syncthreads();

    int w4 = (tid & 31) * 4;
    int s  = tid >> 5;                  // 0..7 -> h pairs [s*8, s*8+8)
    float4 vr[KK];
    #pragma unroll
    for (int k = 0; k < KK; k++) vr[k] = *(const float4*)(vs + k*132 + w4);

    float* op = out + (size_t)bf * IMG + w4;
    #pragma unroll 4
    for (int pp = 0; pp < 8; pp++) {
        int h = s*8 + pp;               // lo row; hi = 127-h
        float xn = xs[h], x2 = xn + xn;
        float4 E, O;
        E.x = vr[0].x; E.y = vr[0].y; E.z = vr[0].z; E.w = vr[0].w;
        float t0 = 1.0f, t1 = xn;
        O.x = t1*vr[1].x; O.y = t1*vr[1].y; O.z = t1*vr[1].z; O.w = t1*vr[1].w;
        #pragma unroll
        for (int k = 2; k < KK; k++) {
            float t2 = x2*t1 - t0;
            if ((k & 1) == 0) {
                E.x += t2*vr[k].x; E.y += t2*vr[k].y;
                E.z += t2*vr[k].z; E.w += t2*vr[k].w;
            } else {
                O.x += t2*vr[k].x; O.y += t2*vr[k].y;
                O.z += t2*vr[k].z; O.w += t2*vr[k].w;
            }
            t0 = t1; t1 = t2;
        }
        float4 lo, hi;
        lo.x = E.x + O.x; lo.y = E.y + O.y; lo.z = E.z + O.z; lo.w = E.w + O.w;
        hi.x = E.x - O.x; hi.y = E.y - O.y; hi.z = E.z - O.z; hi.w = E.w - O.w;
        *(float4*)(op + h*WW)       = lo;
        *(float4*)(op + (127-h)*WW) = hi;
    }
}

// ---------------------------------------------------------------------------
extern "C" void kernel_launch(void* const* d_in, const int* in_sizes, int n_in,
                              void* d_out, int out_size) {
    const float* x  = (const float*)d_in[0];
    const float* Ww = (const float*)d_in[1];
    const float* Wh = (const float*)d_in[2];
    float* out = (float*)d_out;

    kA_setup_wc<<<1 + KK2, 256>>>(Ww, Wh);
    k1_analysis<<<BC, 128>>>(x);
    k_mix<<<KK2*4, 256>>>();
    k4_synth<<<BF, 256>>>(out);
}